// round 11
// baseline (speedup 1.0000x reference)
#include <cuda_runtime.h>
#include <cuda_fp16.h>
#include <cstdint>

#define B_SZ 8
#define T_SZ 4096
#define D_SZ 1024
#define H_SZ 1024
#define M_TOT (B_SZ * T_SZ)   // 32768
#define NC 32                  // chunks along T (scan)
#define CL 128                 // chunk length (NC*CL = T_SZ)

// Scratch (static __device__ arrays — no allocation in kernel_launch)
__device__ float g_k [M_TOT * H_SZ];   // a = sigmoid(-k)
__device__ float g_th[M_TOT * H_SZ];   // b = sigmoid(k)*g(th)
__device__ float g_A   [B_SZ * NC * H_SZ];
__device__ float g_Bc  [B_SZ * NC * H_SZ];
__device__ float g_hini[B_SZ * NC * H_SZ];
__device__ __half g_xh [M_TOT * D_SZ];  // fp16 copies for tensor path
__device__ __half g_wzh[H_SZ * D_SZ];
__device__ __half g_whh[H_SZ * D_SZ];

// ===========================================================================
// Helpers
// ===========================================================================
__device__ __forceinline__ uint32_t smem_u32(const void* p) {
    uint32_t a;
    asm("{ .reg .u64 t; cvta.to.shared.u64 t, %1; cvt.u32.u64 %0, t; }" : "=r"(a) : "l"(p));
    return a;
}
__device__ __forceinline__ void cp_async16(uint32_t dst, const void* src) {
    asm volatile("cp.async.cg.shared.global [%0], [%1], 16;\n" :: "r"(dst), "l"(src));
}
#define CP_COMMIT() asm volatile("cp.async.commit_group;\n" ::: "memory")
#define CP_WAIT(N)  asm volatile("cp.async.wait_group %0;\n" :: "n"(N) : "memory")

__device__ __forceinline__ void ldsm_x4(uint32_t& r0, uint32_t& r1,
                                        uint32_t& r2, uint32_t& r3, uint32_t addr) {
    asm volatile("ldmatrix.sync.aligned.m8n8.x4.shared.b16 {%0,%1,%2,%3}, [%4];"
                 : "=r"(r0), "=r"(r1), "=r"(r2), "=r"(r3) : "r"(addr));
}

__device__ __forceinline__ void mma_f16(float& c0, float& c1, float& c2, float& c3,
                                        uint32_t a0, uint32_t a1, uint32_t a2, uint32_t a3,
                                        uint32_t b0, uint32_t b1) {
    asm volatile(
        "mma.sync.aligned.m16n8k16.row.col.f32.f16.f16.f32 "
        "{%0,%1,%2,%3}, {%4,%5,%6,%7}, {%8,%9}, {%0,%1,%2,%3};"
        : "+f"(c0), "+f"(c1), "+f"(c2), "+f"(c3)
        : "r"(a0), "r"(a1), "r"(a2), "r"(a3), "r"(b0), "r"(b1));
}

// ===========================================================================
// fp32 -> fp16 conversion pass (8 elems/thread, vectorized)
// ===========================================================================
__global__ __launch_bounds__(256) void cvt_kernel(const float* __restrict__ src,
                                                  __half* __restrict__ dst)
{
    size_t i = ((size_t)blockIdx.x * 256 + threadIdx.x) * 8;
    float4 v0 = *reinterpret_cast<const float4*>(src + i);
    float4 v1 = *reinterpret_cast<const float4*>(src + i + 4);
    __half2 h[4];
    h[0] = __floats2half2_rn(v0.x, v0.y);
    h[1] = __floats2half2_rn(v0.z, v0.w);
    h[2] = __floats2half2_rn(v1.x, v1.y);
    h[3] = __floats2half2_rn(v1.z, v1.w);
    *reinterpret_cast<uint4*>(dst + i) = *reinterpret_cast<uint4*>(h);
}

// ===========================================================================
// Fused GEMM (mma.sync fp16, fp32 accum, ldmatrix) + bias + gate epilogue.
// 256 threads = 8 warps: 2 warp-rows (64 M) x 4 warp-cols (64 N).
// CTA tile M=128 x N=256 (128 h); N interleaves (Wz,Wh): even->k, odd->th.
// Warp tile 64x64: 8 LDSM : 32 MMA per k-step (2x better mix than 64x32).
// 1 CTA/SM, <=255 regs/thread.
// ===========================================================================
#define BM 128
#define BN 256
#define BK 64                           // halfs per chunk = 4 x k16 steps
#define STAGES 3
#define PITCHW 36                       // 32-bit words per smem row
#define PITCHB (PITCHW * 4)             // 144 bytes
#define A_WORDS (BM * PITCHW)           // 4608
#define B_WORDS (BN * PITCHW)           // 9216
#define STAGE_WORDS (A_WORDS + B_WORDS) // 13824
#define SMEM_DYN (STAGES * STAGE_WORDS * 4)   // 165888 bytes
#define NCHUNK (D_SZ / BK)              // 16

__global__ void __launch_bounds__(256, 1)
gemm_kernel(const float* __restrict__ bz,
            const float* __restrict__ bh)
{
    extern __shared__ uint32_t smem[];
    const uint32_t smem_b = smem_u32(smem);

    const int tid = threadIdx.x;
    const int wid = tid >> 5;
    const int lid = tid & 31;
    const int gr  = lid >> 2;    // 0..7
    const int gc  = lid & 3;     // 0..3
    const int wm  = wid & 1;     // 2 warp rows (64 M each)
    const int wn  = wid >> 1;    // 4 warp cols (64 N each)
    const int m0  = blockIdx.y * BM;
    const int h0  = blockIdx.x * (BN / 2);   // 128 h per CTA

    // ---- per-lane ldmatrix byte offsets (within a stage)
    const uint32_t aLane = (uint32_t)(wm * 64 + (lid & 15)) * PITCHB + (uint32_t)(lid >> 4) * 16;
    const uint32_t bLane = A_WORDS * 4
        + (uint32_t)(wn * 64 + ((lid >> 4) & 1) * 8 + (lid & 7)) * PITCHB
        + (uint32_t)((lid >> 3) & 1) * 16;

    // ---- async loader: one K-chunk (64 halfs = 128B/row) into stage s
    auto load_chunk = [&](int c, int s) {
        const int k0 = c * BK;
        const uint32_t abase = smem_b + (uint32_t)s * STAGE_WORDS * 4;
        const uint32_t bbase = abase + A_WORDS * 4;
        // A: 128 rows x 8 x 16B = 1024 -> 4/thread
        #pragma unroll
        for (int j = 0; j < 4; j++) {
            int idx = tid + j * 256;
            int r = idx >> 3, q = idx & 7;
            cp_async16(abase + r * PITCHB + q * 16,
                       &g_xh[(size_t)(m0 + r) * D_SZ + k0 + q * 8]);
        }
        // B: 256 rows x 8 x 16B = 2048 -> 8/thread (interleaved Wz/Wh)
        #pragma unroll
        for (int j = 0; j < 8; j++) {
            int idx = tid + j * 256;
            int n = idx >> 3, q = idx & 7;
            const __half* W = (n & 1) ? g_whh : g_wzh;
            cp_async16(bbase + n * PITCHB + q * 16,
                       &W[(size_t)(h0 + (n >> 1)) * D_SZ + k0 + q * 8]);
        }
    };

    float acc[4][8][4];
    #pragma unroll
    for (int i = 0; i < 4; i++)
        #pragma unroll
        for (int j = 0; j < 8; j++)
            #pragma unroll
            for (int t = 0; t < 4; t++)
                acc[i][j][t] = 0.0f;

    load_chunk(0, 0); CP_COMMIT();
    load_chunk(1, 1); CP_COMMIT();

    for (int i = 0; i < NCHUNK; i++) {
        if (i == NCHUNK - 1) { CP_WAIT(0); } else { CP_WAIT(1); }
        // Single barrier: makes chunk i visible AND certifies all warps are
        // done with chunk i-1, so its stage (== (i+2)%3) may be overwritten.
        __syncthreads();
        if (i + 2 < NCHUNK) { load_chunk(i + 2, (i + 2) % STAGES); CP_COMMIT(); }

        const uint32_t sbase = smem_b + (uint32_t)(i % STAGES) * STAGE_WORDS * 4;

        #pragma unroll
        for (int ks = 0; ks < 4; ks++) {
            const uint32_t koff = (uint32_t)ks * 32;   // 8 words = 32B per k16 step
            uint32_t af[4][4], bf[4][4];
            #pragma unroll
            for (int mi = 0; mi < 4; mi++)
                ldsm_x4(af[mi][0], af[mi][1], af[mi][2], af[mi][3],
                        sbase + aLane + (uint32_t)mi * 16 * PITCHB + koff);
            #pragma unroll
            for (int p = 0; p < 4; p++)
                ldsm_x4(bf[p][0], bf[p][1], bf[p][2], bf[p][3],
                        sbase + bLane + (uint32_t)p * 16 * PITCHB + koff);
            #pragma unroll
            for (int mi = 0; mi < 4; mi++) {
                #pragma unroll
                for (int p = 0; p < 4; p++) {
                    mma_f16(acc[mi][2*p  ][0], acc[mi][2*p  ][1],
                            acc[mi][2*p  ][2], acc[mi][2*p  ][3],
                            af[mi][0], af[mi][1], af[mi][2], af[mi][3],
                            bf[p][0], bf[p][1]);
                    mma_f16(acc[mi][2*p+1][0], acc[mi][2*p+1][1],
                            acc[mi][2*p+1][2], acc[mi][2*p+1][3],
                            af[mi][0], af[mi][1], af[mi][2], af[mi][3],
                            bf[p][2], bf[p][3]);
                }
            }
        }
    }

    // ---- epilogue: gates in registers, scalar stores
    #pragma unroll
    for (int mi = 0; mi < 4; mi++) {
        #pragma unroll
        for (int nj = 0; nj < 8; nj++) {
            const int h = h0 + wn * 32 + nj * 4 + gc;
            const float bzv = __ldg(&bz[h]);
            const float bhv = __ldg(&bh[h]);
            #pragma unroll
            for (int half = 0; half < 2; half++) {
                const int m = m0 + wm * 64 + mi * 16 + gr + half * 8;
                float k  = acc[mi][nj][half * 2 + 0] + bzv;
                float th = acc[mi][nj][half * 2 + 1] + bhv;
                float em  = __expf(-fabsf(k));
                float inv = 1.0f / (1.0f + em);
                float z, a;
                if (k >= 0.0f) { z = inv;      a = em * inv; }
                else           { z = em * inv; a = inv;      }
                float g;
                if (th >= 0.0f) g = th + 0.5f;
                else            g = 1.0f / (1.0f + __expf(-th));
                g_k [(size_t)m * H_SZ + h] = a;
                g_th[(size_t)m * H_SZ + h] = z * g;
            }
        }
    }
}

// ===========================================================================
// Chunked scan: h[t] = a[t]*h[t-1] + b[t], h[-1] = 0
// ===========================================================================
__global__ __launch_bounds__(256) void scan1_kernel()
{
    int idx = blockIdx.x * 256 + threadIdx.x;   // 0 .. B*NC*H-1
    int h  = idx & (H_SZ - 1);
    int bc = idx >> 10;
    int c  = bc & (NC - 1);
    int b  = bc >> 5;
    size_t base = ((size_t)b * T_SZ + (size_t)c * CL) * H_SZ + h;

    float A = 1.0f, acc = 0.0f;
    #pragma unroll 4
    for (int t = 0; t < CL; t++) {
        float a  = g_k [base + (size_t)t * H_SZ];
        float bb = g_th[base + (size_t)t * H_SZ];
        A *= a;
        acc = fmaf(a, acc, bb);
    }
    g_A [idx] = A;
    g_Bc[idx] = acc;
}

__global__ __launch_bounds__(256) void scan2_kernel()
{
    int idx = blockIdx.x * 256 + threadIdx.x;   // 0 .. B*H-1
    int h = idx & (H_SZ - 1);
    int b = idx >> 10;
    float carry = 0.0f;
    #pragma unroll
    for (int c = 0; c < NC; c++) {
        int j = (b * NC + c) * H_SZ + h;
        g_hini[j] = carry;
        carry = fmaf(g_A[j], carry, g_Bc[j]);
    }
}

__global__ __launch_bounds__(256) void scan3_kernel(float* __restrict__ out)
{
    int idx = blockIdx.x * 256 + threadIdx.x;
    int h  = idx & (H_SZ - 1);
    int bc = idx >> 10;
    int c  = bc & (NC - 1);
    int b  = bc >> 5;
    size_t base = ((size_t)b * T_SZ + (size_t)c * CL) * H_SZ + h;

    float acc = g_hini[idx];
    #pragma unroll 4
    for (int t = 0; t < CL; t++) {
        float a  = g_k [base + (size_t)t * H_SZ];
        float bb = g_th[base + (size_t)t * H_SZ];
        acc = fmaf(a, acc, bb);
        out[base + (size_t)t * H_SZ] = acc;
    }
}

// ===========================================================================
extern "C" void kernel_launch(void* const* d_in, const int* in_sizes, int n_in,
                              void* d_out, int out_size)
{
    const float* x  = (const float*)d_in[0];
    const float* Wz = (const float*)d_in[1];
    const float* bz = (const float*)d_in[2];
    const float* Wh = (const float*)d_in[3];
    const float* bh = (const float*)d_in[4];
    float* out = (float*)d_out;

    cudaFuncSetAttribute(gemm_kernel,
                         cudaFuncAttributeMaxDynamicSharedMemorySize, SMEM_DYN);

    // fp32 -> fp16 conversion
    __half* xh;  cudaGetSymbolAddress((void**)&xh,  g_xh);
    __half* wzh; cudaGetSymbolAddress((void**)&wzh, g_wzh);
    __half* whh; cudaGetSymbolAddress((void**)&whh, g_whh);
    cvt_kernel<<<(M_TOT * D_SZ) / (256 * 8), 256>>>(x,  xh);
    cvt_kernel<<<(H_SZ * D_SZ) / (256 * 8), 256>>>(Wz, wzh);
    cvt_kernel<<<(H_SZ * D_SZ) / (256 * 8), 256>>>(Wh, whh);

    dim3 ggrid(H_SZ / (BN / 2), M_TOT / BM);   // (8, 256)
    gemm_kernel<<<ggrid, 256, SMEM_DYN>>>(bz, bh);

    scan1_kernel<<<(B_SZ * NC * H_SZ) / 256, 256>>>();
    scan2_kernel<<<(B_SZ * H_SZ) / 256, 256>>>();
    scan3_kernel<<<(B_SZ * NC * H_SZ) / 256, 256>>>(out);
}

// round 13
// speedup vs baseline: 1.2499x; 1.2499x over previous
#include <cuda_runtime.h>
#include <cuda_fp16.h>
#include <cstdint>

#define B_SZ 8
#define T_SZ 4096
#define D_SZ 1024
#define H_SZ 1024
#define M_TOT (B_SZ * T_SZ)   // 32768
#define NC 32                  // chunks along T (scan)
#define CL 128                 // chunk length (NC*CL = T_SZ)

// Scratch (static __device__ arrays — no allocation in kernel_launch)
__device__ float g_k [M_TOT * H_SZ];   // a = sigmoid(-k)
__device__ float g_th[M_TOT * H_SZ];   // b = sigmoid(k)*g(th)
__device__ float g_A   [B_SZ * NC * H_SZ];
__device__ float g_Bc  [B_SZ * NC * H_SZ];
__device__ float g_hini[B_SZ * NC * H_SZ];
__device__ __half g_xh [M_TOT * D_SZ];  // fp16 copies for tensor path
__device__ __half g_wzh[H_SZ * D_SZ];
__device__ __half g_whh[H_SZ * D_SZ];

// ===========================================================================
// Helpers
// ===========================================================================
__device__ __forceinline__ uint32_t smem_u32(const void* p) {
    uint32_t a;
    asm("{ .reg .u64 t; cvta.to.shared.u64 t, %1; cvt.u32.u64 %0, t; }" : "=r"(a) : "l"(p));
    return a;
}
__device__ __forceinline__ void cp_async16(uint32_t dst, const void* src) {
    asm volatile("cp.async.cg.shared.global [%0], [%1], 16;\n" :: "r"(dst), "l"(src));
}
#define CP_COMMIT() asm volatile("cp.async.commit_group;\n" ::: "memory")
#define CP_WAIT(N)  asm volatile("cp.async.wait_group %0;\n" :: "n"(N) : "memory")

__device__ __forceinline__ void ldsm_x4(uint32_t& r0, uint32_t& r1,
                                        uint32_t& r2, uint32_t& r3, uint32_t addr) {
    asm volatile("ldmatrix.sync.aligned.m8n8.x4.shared.b16 {%0,%1,%2,%3}, [%4];"
                 : "=r"(r0), "=r"(r1), "=r"(r2), "=r"(r3) : "r"(addr));
}

__device__ __forceinline__ void mma_f16(float& c0, float& c1, float& c2, float& c3,
                                        uint32_t a0, uint32_t a1, uint32_t a2, uint32_t a3,
                                        uint32_t b0, uint32_t b1) {
    asm volatile(
        "mma.sync.aligned.m16n8k16.row.col.f32.f16.f16.f32 "
        "{%0,%1,%2,%3}, {%4,%5,%6,%7}, {%8,%9}, {%0,%1,%2,%3};"
        : "+f"(c0), "+f"(c1), "+f"(c2), "+f"(c3)
        : "r"(a0), "r"(a1), "r"(a2), "r"(a3), "r"(b0), "r"(b1));
}

// ===========================================================================
// fp32 -> fp16 conversion pass (8 elems/thread, vectorized)
// ===========================================================================
__global__ __launch_bounds__(256) void cvt_kernel(const float* __restrict__ src,
                                                  __half* __restrict__ dst)
{
    size_t i = ((size_t)blockIdx.x * 256 + threadIdx.x) * 8;
    float4 v0 = *reinterpret_cast<const float4*>(src + i);
    float4 v1 = *reinterpret_cast<const float4*>(src + i + 4);
    __half2 h[4];
    h[0] = __floats2half2_rn(v0.x, v0.y);
    h[1] = __floats2half2_rn(v0.z, v0.w);
    h[2] = __floats2half2_rn(v1.x, v1.y);
    h[3] = __floats2half2_rn(v1.z, v1.w);
    *reinterpret_cast<uint4*>(dst + i) = *reinterpret_cast<uint4*>(h);
}

// ===========================================================================
// Fused GEMM (mma.sync fp16, fp32 accum, ldmatrix) + gates + chunk summary.
// 256 threads = 8 warps: 2 warp-rows (64 M) x 4 warp-cols (32 N).
// CTA tile M=128 x N=128 (64 h); N interleaves (Wz,Wh): even->k, odd->th.
// Each CTA tile is EXACTLY one scan chunk (128 t x 64 h), so the epilogue
// stages a,b in smem, writes them coalesced, and computes the per-chunk
// scan summaries (A = prod a, Bc = chunk-local scan tail) -> scan1 removed.
// 2 CTAs/SM; single barrier per K-chunk (3-stage cp.async pipeline).
// ===========================================================================
#define BM 128
#define BN 128
#define BK 64                           // halfs per chunk = 4 x k16 steps
#define STAGES 3
#define PITCHW 36                       // 32-bit words per smem row
#define PITCHB (PITCHW * 4)             // 144 bytes
#define A_WORDS (BM * PITCHW)           // 4608
#define B_WORDS (BN * PITCHW)           // 4608
#define STAGE_WORDS (A_WORDS + B_WORDS) // 9216
#define SMEM_DYN (STAGES * STAGE_WORDS * 4)   // 110592 bytes
#define NCHUNK (D_SZ / BK)              // 16
#define EPI_PITCH 65                    // floats per staged row (conflict-free)

__global__ void __launch_bounds__(256, 2)
gemm_kernel(const float* __restrict__ bz,
            const float* __restrict__ bh)
{
    extern __shared__ uint32_t smem[];
    const uint32_t smem_b = smem_u32(smem);

    const int tid = threadIdx.x;
    const int wid = tid >> 5;
    const int lid = tid & 31;
    const int gr  = lid >> 2;    // 0..7
    const int gc  = lid & 3;     // 0..3
    const int wm  = wid & 1;     // 2 warp rows (64 M each)
    const int wn  = wid >> 1;    // 4 warp cols (32 N each)
    const int m0  = blockIdx.y * BM;
    const int h0  = blockIdx.x * (BN / 2);   // 64 h per CTA

    // ---- per-lane ldmatrix byte offsets (within a stage)
    const uint32_t aLane = (uint32_t)(wm * 64 + (lid & 15)) * PITCHB + (uint32_t)(lid >> 4) * 16;
    const uint32_t bLane = A_WORDS * 4
        + (uint32_t)(wn * 32 + ((lid >> 4) & 1) * 8 + (lid & 7)) * PITCHB
        + (uint32_t)((lid >> 3) & 1) * 16;

    // ---- async loader: one K-chunk (64 halfs = 128B/row) into stage s
    auto load_chunk = [&](int c, int s) {
        const int k0 = c * BK;
        const uint32_t abase = smem_b + (uint32_t)s * STAGE_WORDS * 4;
        const uint32_t bbase = abase + A_WORDS * 4;
        #pragma unroll
        for (int j = 0; j < 4; j++) {
            int idx = tid + j * 256;
            int r = idx >> 3, q = idx & 7;
            cp_async16(abase + r * PITCHB + q * 16,
                       &g_xh[(size_t)(m0 + r) * D_SZ + k0 + q * 8]);
        }
        #pragma unroll
        for (int j = 0; j < 4; j++) {
            int idx = tid + j * 256;
            int n = idx >> 3, q = idx & 7;
            const __half* W = (n & 1) ? g_whh : g_wzh;
            cp_async16(bbase + n * PITCHB + q * 16,
                       &W[(size_t)(h0 + (n >> 1)) * D_SZ + k0 + q * 8]);
        }
    };

    float acc[4][4][4];
    #pragma unroll
    for (int i = 0; i < 4; i++)
        #pragma unroll
        for (int j = 0; j < 4; j++)
            #pragma unroll
            for (int t = 0; t < 4; t++)
                acc[i][j][t] = 0.0f;

    load_chunk(0, 0); CP_COMMIT();
    load_chunk(1, 1); CP_COMMIT();

    for (int i = 0; i < NCHUNK; i++) {
        if (i == NCHUNK - 1) { CP_WAIT(0); } else { CP_WAIT(1); }
        __syncthreads();
        if (i + 2 < NCHUNK) { load_chunk(i + 2, (i + 2) % STAGES); CP_COMMIT(); }

        const uint32_t sbase = smem_b + (uint32_t)(i % STAGES) * STAGE_WORDS * 4;

        #pragma unroll
        for (int ks = 0; ks < 4; ks++) {
            const uint32_t koff = (uint32_t)ks * 32;
            uint32_t af[4][4], bf[2][4];
            #pragma unroll
            for (int mi = 0; mi < 4; mi++)
                ldsm_x4(af[mi][0], af[mi][1], af[mi][2], af[mi][3],
                        sbase + aLane + (uint32_t)mi * 16 * PITCHB + koff);
            #pragma unroll
            for (int p = 0; p < 2; p++)
                ldsm_x4(bf[p][0], bf[p][1], bf[p][2], bf[p][3],
                        sbase + bLane + (uint32_t)p * 16 * PITCHB + koff);
            #pragma unroll
            for (int mi = 0; mi < 4; mi++) {
                #pragma unroll
                for (int p = 0; p < 2; p++) {
                    mma_f16(acc[mi][2*p  ][0], acc[mi][2*p  ][1],
                            acc[mi][2*p  ][2], acc[mi][2*p  ][3],
                            af[mi][0], af[mi][1], af[mi][2], af[mi][3],
                            bf[p][0], bf[p][1]);
                    mma_f16(acc[mi][2*p+1][0], acc[mi][2*p+1][1],
                            acc[mi][2*p+1][2], acc[mi][2*p+1][3],
                            af[mi][0], af[mi][1], af[mi][2], af[mi][3],
                            bf[p][2], bf[p][3]);
                }
            }
        }
    }

    // ================= epilogue =================
    // 1) gate math in registers, stage a,b into smem (pipeline smem is free
    //    after the barrier below: every warp has finished its LDSMs).
    __syncthreads();
    float* sa = (float*)smem;                    // [128][EPI_PITCH]
    float* sb = sa + BM * EPI_PITCH;             // [128][EPI_PITCH]

    #pragma unroll
    for (int mi = 0; mi < 4; mi++) {
        #pragma unroll
        for (int nj = 0; nj < 4; nj++) {
            const int hl = wn * 16 + nj * 4 + gc;
            const float bzv = __ldg(&bz[h0 + hl]);
            const float bhv = __ldg(&bh[h0 + hl]);
            #pragma unroll
            for (int half = 0; half < 2; half++) {
                const int r = wm * 64 + mi * 16 + gr + half * 8;
                float k  = acc[mi][nj][half * 2 + 0] + bzv;
                float th = acc[mi][nj][half * 2 + 1] + bhv;
                float em  = __expf(-fabsf(k));
                float inv = 1.0f / (1.0f + em);
                float z, a;
                if (k >= 0.0f) { z = inv;      a = em * inv; }
                else           { z = em * inv; a = inv;      }
                float g;
                if (th >= 0.0f) g = th + 0.5f;
                else            g = 1.0f / (1.0f + __expf(-th));
                sa[r * EPI_PITCH + hl] = a;
                sb[r * EPI_PITCH + hl] = z * g;
            }
        }
    }
    __syncthreads();

    // 2) coalesced smem -> global stores of a,b (256B per row segment)
    #pragma unroll 4
    for (int e = tid; e < BM * 64; e += 256) {
        const int m = e >> 6, hl = e & 63;
        g_k [(size_t)(m0 + m) * H_SZ + h0 + hl] = sa[m * EPI_PITCH + hl];
        g_th[(size_t)(m0 + m) * H_SZ + h0 + hl] = sb[m * EPI_PITCH + hl];
    }

    // 3) per-chunk scan summaries: this tile IS one chunk (b, c).
    if (tid < 64) {
        const int hl = tid;
        float A = 1.0f, accs = 0.0f;
        #pragma unroll 8
        for (int t = 0; t < CL; t++) {
            float a  = sa[t * EPI_PITCH + hl];
            float bb = sb[t * EPI_PITCH + hl];
            A *= a;
            accs = fmaf(a, accs, bb);
        }
        const int bidx = m0 >> 12;           // / T_SZ
        const int cidx = (m0 & (T_SZ - 1)) >> 7;   // / CL
        const int j = (bidx * NC + cidx) * H_SZ + h0 + hl;
        g_A [j] = A;
        g_Bc[j] = accs;
    }
}

// ===========================================================================
// scan2: carry across chunks per (b,h)
// ===========================================================================
__global__ __launch_bounds__(256) void scan2_kernel()
{
    int idx = blockIdx.x * 256 + threadIdx.x;   // 0 .. B*H-1
    int h = idx & (H_SZ - 1);
    int b = idx >> 10;
    float carry = 0.0f;
    #pragma unroll
    for (int c = 0; c < NC; c++) {
        int j = (b * NC + c) * H_SZ + h;
        g_hini[j] = carry;
        carry = fmaf(g_A[j], carry, g_Bc[j]);
    }
}

// ===========================================================================
// scan3: rescan with carries, write output
// ===========================================================================
__global__ __launch_bounds__(256) void scan3_kernel(float* __restrict__ out)
{
    int idx = blockIdx.x * 256 + threadIdx.x;
    int h  = idx & (H_SZ - 1);
    int bc = idx >> 10;
    int c  = bc & (NC - 1);
    int b  = bc >> 5;
    size_t base = ((size_t)b * T_SZ + (size_t)c * CL) * H_SZ + h;

    float acc = g_hini[idx];
    #pragma unroll 4
    for (int t = 0; t < CL; t++) {
        float a  = g_k [base + (size_t)t * H_SZ];
        float bb = g_th[base + (size_t)t * H_SZ];
        acc = fmaf(a, acc, bb);
        out[base + (size_t)t * H_SZ] = acc;
    }
}

// ===========================================================================
extern "C" void kernel_launch(void* const* d_in, const int* in_sizes, int n_in,
                              void* d_out, int out_size)
{
    const float* x  = (const float*)d_in[0];
    const float* Wz = (const float*)d_in[1];
    const float* bz = (const float*)d_in[2];
    const float* Wh = (const float*)d_in[3];
    const float* bh = (const float*)d_in[4];
    float* out = (float*)d_out;

    cudaFuncSetAttribute(gemm_kernel,
                         cudaFuncAttributeMaxDynamicSharedMemorySize, SMEM_DYN);

    // fp32 -> fp16 conversion
    __half* xh;  cudaGetSymbolAddress((void**)&xh,  g_xh);
    __half* wzh; cudaGetSymbolAddress((void**)&wzh, g_wzh);
    __half* whh; cudaGetSymbolAddress((void**)&whh, g_whh);
    cvt_kernel<<<(M_TOT * D_SZ) / (256 * 8), 256>>>(x,  xh);
    cvt_kernel<<<(H_SZ * D_SZ) / (256 * 8), 256>>>(Wz, wzh);
    cvt_kernel<<<(H_SZ * D_SZ) / (256 * 8), 256>>>(Wh, whh);

    dim3 ggrid(H_SZ / (BN / 2), M_TOT / BM);   // (16, 256)
    gemm_kernel<<<ggrid, 256, SMEM_DYN>>>(bz, bh);

    scan2_kernel<<<(B_SZ * H_SZ) / 256, 256>>>();
    scan3_kernel<<<(B_SZ * NC * H_SZ) / 256, 256>>>(out);
}

// round 15
// speedup vs baseline: 1.3580x; 1.0865x over previous
#include <cuda_runtime.h>
#include <cuda_fp16.h>
#include <cstdint>

#define B_SZ 8
#define T_SZ 4096
#define D_SZ 1024
#define H_SZ 1024
#define M_TOT (B_SZ * T_SZ)   // 32768
#define NC 32                  // chunks along T (scan)
#define CL 128                 // chunk length (NC*CL = T_SZ)

// Scratch (static __device__ arrays — no allocation in kernel_launch)
__device__ __half2 g_ab[M_TOT * H_SZ]; // packed (a, b) per element
__device__ float g_A [B_SZ * NC * H_SZ];
__device__ float g_Bc[B_SZ * NC * H_SZ];
__device__ __half g_xh [M_TOT * D_SZ]; // fp16 copies for tensor path
__device__ __half g_wzh[H_SZ * D_SZ];
__device__ __half g_whh[H_SZ * D_SZ];

// ===========================================================================
// Helpers
// ===========================================================================
__device__ __forceinline__ uint32_t smem_u32(const void* p) {
    uint32_t a;
    asm("{ .reg .u64 t; cvta.to.shared.u64 t, %1; cvt.u32.u64 %0, t; }" : "=r"(a) : "l"(p));
    return a;
}
__device__ __forceinline__ void cp_async16(uint32_t dst, const void* src) {
    asm volatile("cp.async.cg.shared.global [%0], [%1], 16;\n" :: "r"(dst), "l"(src));
}
#define CP_COMMIT() asm volatile("cp.async.commit_group;\n" ::: "memory")
#define CP_WAIT(N)  asm volatile("cp.async.wait_group %0;\n" :: "n"(N) : "memory")

__device__ __forceinline__ void ldsm_x4(uint32_t& r0, uint32_t& r1,
                                        uint32_t& r2, uint32_t& r3, uint32_t addr) {
    asm volatile("ldmatrix.sync.aligned.m8n8.x4.shared.b16 {%0,%1,%2,%3}, [%4];"
                 : "=r"(r0), "=r"(r1), "=r"(r2), "=r"(r3) : "r"(addr));
}

__device__ __forceinline__ void mma_f16(float& c0, float& c1, float& c2, float& c3,
                                        uint32_t a0, uint32_t a1, uint32_t a2, uint32_t a3,
                                        uint32_t b0, uint32_t b1) {
    asm volatile(
        "mma.sync.aligned.m16n8k16.row.col.f32.f16.f16.f32 "
        "{%0,%1,%2,%3}, {%4,%5,%6,%7}, {%8,%9}, {%0,%1,%2,%3};"
        : "+f"(c0), "+f"(c1), "+f"(c2), "+f"(c3)
        : "r"(a0), "r"(a1), "r"(a2), "r"(a3), "r"(b0), "r"(b1));
}

// ===========================================================================
// fp32 -> fp16 conversion pass (8 elems/thread, vectorized)
// ===========================================================================
__global__ __launch_bounds__(256) void cvt_kernel(const float* __restrict__ src,
                                                  __half* __restrict__ dst)
{
    size_t i = ((size_t)blockIdx.x * 256 + threadIdx.x) * 8;
    float4 v0 = *reinterpret_cast<const float4*>(src + i);
    float4 v1 = *reinterpret_cast<const float4*>(src + i + 4);
    __half2 h[4];
    h[0] = __floats2half2_rn(v0.x, v0.y);
    h[1] = __floats2half2_rn(v0.z, v0.w);
    h[2] = __floats2half2_rn(v1.x, v1.y);
    h[3] = __floats2half2_rn(v1.z, v1.w);
    *reinterpret_cast<uint4*>(dst + i) = *reinterpret_cast<uint4*>(h);
}

// ===========================================================================
// Fused GEMM (mma.sync fp16, fp32 accum, ldmatrix) + gates + chunk summary.
// 256 threads = 8 warps: 2 warp-rows (64 M) x 4 warp-cols (32 N).
// CTA tile M=128 x N=128 (64 h); N interleaves (Wz,Wh): even->k, odd->th.
// Epilogue: gates -> smem (fp32), packed half2 (a,b) -> g_ab coalesced,
// per-chunk scan summaries (fp32) -> g_A/g_Bc. 2 CTAs/SM; 3-stage cp.async.
// ===========================================================================
#define BM 128
#define BN 128
#define BK 64                           // halfs per chunk = 4 x k16 steps
#define STAGES 3
#define PITCHW 36                       // 32-bit words per smem row
#define PITCHB (PITCHW * 4)             // 144 bytes
#define A_WORDS (BM * PITCHW)           // 4608
#define B_WORDS (BN * PITCHW)           // 4608
#define STAGE_WORDS (A_WORDS + B_WORDS) // 9216
#define SMEM_DYN (STAGES * STAGE_WORDS * 4)   // 110592 bytes
#define NCHUNK (D_SZ / BK)              // 16
#define EPI_PITCH 65                    // floats per staged row (conflict-free)

__global__ void __launch_bounds__(256, 2)
gemm_kernel(const float* __restrict__ bz,
            const float* __restrict__ bh)
{
    extern __shared__ uint32_t smem[];
    const uint32_t smem_b = smem_u32(smem);

    const int tid = threadIdx.x;
    const int wid = tid >> 5;
    const int lid = tid & 31;
    const int gr  = lid >> 2;    // 0..7
    const int gc  = lid & 3;     // 0..3
    const int wm  = wid & 1;     // 2 warp rows (64 M each)
    const int wn  = wid >> 1;    // 4 warp cols (32 N each)
    const int m0  = blockIdx.y * BM;
    const int h0  = blockIdx.x * (BN / 2);   // 64 h per CTA

    // ---- per-lane ldmatrix byte offsets (within a stage)
    const uint32_t aLane = (uint32_t)(wm * 64 + (lid & 15)) * PITCHB + (uint32_t)(lid >> 4) * 16;
    const uint32_t bLane = A_WORDS * 4
        + (uint32_t)(wn * 32 + ((lid >> 4) & 1) * 8 + (lid & 7)) * PITCHB
        + (uint32_t)((lid >> 3) & 1) * 16;

    // ---- async loader: one K-chunk (64 halfs = 128B/row) into stage s
    auto load_chunk = [&](int c, int s) {
        const int k0 = c * BK;
        const uint32_t abase = smem_b + (uint32_t)s * STAGE_WORDS * 4;
        const uint32_t bbase = abase + A_WORDS * 4;
        #pragma unroll
        for (int j = 0; j < 4; j++) {
            int idx = tid + j * 256;
            int r = idx >> 3, q = idx & 7;
            cp_async16(abase + r * PITCHB + q * 16,
                       &g_xh[(size_t)(m0 + r) * D_SZ + k0 + q * 8]);
        }
        #pragma unroll
        for (int j = 0; j < 4; j++) {
            int idx = tid + j * 256;
            int n = idx >> 3, q = idx & 7;
            const __half* W = (n & 1) ? g_whh : g_wzh;
            cp_async16(bbase + n * PITCHB + q * 16,
                       &W[(size_t)(h0 + (n >> 1)) * D_SZ + k0 + q * 8]);
        }
    };

    float acc[4][4][4];
    #pragma unroll
    for (int i = 0; i < 4; i++)
        #pragma unroll
        for (int j = 0; j < 4; j++)
            #pragma unroll
            for (int t = 0; t < 4; t++)
                acc[i][j][t] = 0.0f;

    load_chunk(0, 0); CP_COMMIT();
    load_chunk(1, 1); CP_COMMIT();

    for (int i = 0; i < NCHUNK; i++) {
        if (i == NCHUNK - 1) { CP_WAIT(0); } else { CP_WAIT(1); }
        __syncthreads();
        if (i + 2 < NCHUNK) { load_chunk(i + 2, (i + 2) % STAGES); CP_COMMIT(); }

        const uint32_t sbase = smem_b + (uint32_t)(i % STAGES) * STAGE_WORDS * 4;

        #pragma unroll
        for (int ks = 0; ks < 4; ks++) {
            const uint32_t koff = (uint32_t)ks * 32;
            uint32_t af[4][4], bf[2][4];
            #pragma unroll
            for (int mi = 0; mi < 4; mi++)
                ldsm_x4(af[mi][0], af[mi][1], af[mi][2], af[mi][3],
                        sbase + aLane + (uint32_t)mi * 16 * PITCHB + koff);
            #pragma unroll
            for (int p = 0; p < 2; p++)
                ldsm_x4(bf[p][0], bf[p][1], bf[p][2], bf[p][3],
                        sbase + bLane + (uint32_t)p * 16 * PITCHB + koff);
            #pragma unroll
            for (int mi = 0; mi < 4; mi++) {
                #pragma unroll
                for (int p = 0; p < 2; p++) {
                    mma_f16(acc[mi][2*p  ][0], acc[mi][2*p  ][1],
                            acc[mi][2*p  ][2], acc[mi][2*p  ][3],
                            af[mi][0], af[mi][1], af[mi][2], af[mi][3],
                            bf[p][0], bf[p][1]);
                    mma_f16(acc[mi][2*p+1][0], acc[mi][2*p+1][1],
                            acc[mi][2*p+1][2], acc[mi][2*p+1][3],
                            af[mi][0], af[mi][1], af[mi][2], af[mi][3],
                            bf[p][2], bf[p][3]);
                }
            }
        }
    }

    // ================= epilogue =================
    // 1) gate math in registers, stage a,b (fp32) into the pipeline smem.
    __syncthreads();
    float* sa = (float*)smem;                    // [128][EPI_PITCH]
    float* sb = sa + BM * EPI_PITCH;             // [128][EPI_PITCH]

    #pragma unroll
    for (int mi = 0; mi < 4; mi++) {
        #pragma unroll
        for (int nj = 0; nj < 4; nj++) {
            const int hl = wn * 16 + nj * 4 + gc;
            const float bzv = __ldg(&bz[h0 + hl]);
            const float bhv = __ldg(&bh[h0 + hl]);
            #pragma unroll
            for (int half = 0; half < 2; half++) {
                const int r = wm * 64 + mi * 16 + gr + half * 8;
                float k  = acc[mi][nj][half * 2 + 0] + bzv;
                float th = acc[mi][nj][half * 2 + 1] + bhv;
                float em  = __expf(-fabsf(k));
                float inv = 1.0f / (1.0f + em);
                float z, a;
                if (k >= 0.0f) { z = inv;      a = em * inv; }
                else           { z = em * inv; a = inv;      }
                float g;
                if (th >= 0.0f) g = th + 0.5f;
                else            g = 1.0f / (1.0f + __expf(-th));
                sa[r * EPI_PITCH + hl] = a;
                sb[r * EPI_PITCH + hl] = z * g;
            }
        }
    }
    __syncthreads();

    // 2) coalesced packed half2 (a,b) stores
    #pragma unroll 4
    for (int e = tid; e < BM * 64; e += 256) {
        const int m = e >> 6, hl = e & 63;
        g_ab[(size_t)(m0 + m) * H_SZ + h0 + hl] =
            __floats2half2_rn(sa[m * EPI_PITCH + hl], sb[m * EPI_PITCH + hl]);
    }

    // 3) per-chunk scan summaries (fp32): this tile IS one chunk (b, c).
    if (tid < 64) {
        const int hl = tid;
        float A = 1.0f, accs = 0.0f;
        #pragma unroll 8
        for (int t = 0; t < CL; t++) {
            float a  = sa[t * EPI_PITCH + hl];
            float bb = sb[t * EPI_PITCH + hl];
            A *= a;
            accs = fmaf(a, accs, bb);
        }
        const int bidx = m0 >> 12;                 // / T_SZ
        const int cidx = (m0 & (T_SZ - 1)) >> 7;   // / CL
        const int j = (bidx * NC + cidx) * H_SZ + h0 + hl;
        g_A [j] = A;
        g_Bc[j] = accs;
    }
}

// ===========================================================================
// scan3 (scan2 fused): each block computes its own cross-chunk carry from the
// per-chunk summaries, then rescans its chunk from packed half2 (a,b).
// ===========================================================================
__global__ __launch_bounds__(256) void scan3_kernel(float* __restrict__ out)
{
    int idx = blockIdx.x * 256 + threadIdx.x;
    int h  = idx & (H_SZ - 1);
    int bc = idx >> 10;
    int c  = bc & (NC - 1);
    int b  = bc >> 5;

    // carry over chunks 0..c-1 (redundant per block; loads independent -> MLP)
    float carry = 0.0f;
    #pragma unroll 4
    for (int cc = 0; cc < c; cc++) {
        int j = (b * NC + cc) * H_SZ + h;
        carry = fmaf(g_A[j], carry, g_Bc[j]);
    }

    size_t base = ((size_t)b * T_SZ + (size_t)c * CL) * H_SZ + h;
    float acc = carry;
    #pragma unroll 4
    for (int t = 0; t < CL; t++) {
        __half2 ab = g_ab[base + (size_t)t * H_SZ];
        acc = fmaf(__low2float(ab), acc, __high2float(ab));
        out[base + (size_t)t * H_SZ] = acc;
    }
}

// ===========================================================================
extern "C" void kernel_launch(void* const* d_in, const int* in_sizes, int n_in,
                              void* d_out, int out_size)
{
    const float* x  = (const float*)d_in[0];
    const float* Wz = (const float*)d_in[1];
    const float* bz = (const float*)d_in[2];
    const float* Wh = (const float*)d_in[3];
    const float* bh = (const float*)d_in[4];
    float* out = (float*)d_out;

    cudaFuncSetAttribute(gemm_kernel,
                         cudaFuncAttributeMaxDynamicSharedMemorySize, SMEM_DYN);

    // fp32 -> fp16 conversion
    __half* xh;  cudaGetSymbolAddress((void**)&xh,  g_xh);
    __half* wzh; cudaGetSymbolAddress((void**)&wzh, g_wzh);
    __half* whh; cudaGetSymbolAddress((void**)&whh, g_whh);
    cvt_kernel<<<(M_TOT * D_SZ) / (256 * 8), 256>>>(x,  xh);
    cvt_kernel<<<(H_SZ * D_SZ) / (256 * 8), 256>>>(Wz, wzh);
    cvt_kernel<<<(H_SZ * D_SZ) / (256 * 8), 256>>>(Wh, whh);

    dim3 ggrid(H_SZ / (BN / 2), M_TOT / BM);   // (16, 256)
    gemm_kernel<<<ggrid, 256, SMEM_DYN>>>(bz, bh);

    scan3_kernel<<<(B_SZ * NC * H_SZ) / 256, 256>>>(out);
}

// round 17
// speedup vs baseline: 1.3596x; 1.0012x over previous
#include <cuda_runtime.h>
#include <cuda_fp16.h>
#include <cstdint>

#define B_SZ 8
#define T_SZ 4096
#define D_SZ 1024
#define H_SZ 1024
#define M_TOT (B_SZ * T_SZ)   // 32768
#define NC 32                  // chunks along T (scan)
#define CL 128                 // chunk length (NC*CL = T_SZ)
#define NHX 16                 // h-blocks (64 h each)

// Scratch (static __device__ arrays — no allocation in kernel_launch)
__device__ float g_A   [B_SZ * NC * H_SZ];   // per-chunk prod(a)
__device__ float g_Bc  [B_SZ * NC * H_SZ];   // per-chunk local scan tail
__device__ float g_Hinc[B_SZ * NC * H_SZ];   // inclusive prefix at chunk end
__device__ int   g_flag[B_SZ * NC * H_SZ];   // per-lane: 0=none,1=partial,2=inclusive
__device__ int   g_ticket;
__device__ __half g_xh [M_TOT * D_SZ];       // fp16 copies for tensor path
__device__ __half g_wzh[H_SZ * D_SZ];
__device__ __half g_whh[H_SZ * D_SZ];

// ===========================================================================
// Helpers
// ===========================================================================
__device__ __forceinline__ uint32_t smem_u32(const void* p) {
    uint32_t a;
    asm("{ .reg .u64 t; cvta.to.shared.u64 t, %1; cvt.u32.u64 %0, t; }" : "=r"(a) : "l"(p));
    return a;
}
__device__ __forceinline__ void cp_async16(uint32_t dst, const void* src) {
    asm volatile("cp.async.cg.shared.global [%0], [%1], 16;\n" :: "r"(dst), "l"(src));
}
#define CP_COMMIT() asm volatile("cp.async.commit_group;\n" ::: "memory")
#define CP_WAIT(N)  asm volatile("cp.async.wait_group %0;\n" :: "n"(N) : "memory")

__device__ __forceinline__ void ldsm_x4(uint32_t& r0, uint32_t& r1,
                                        uint32_t& r2, uint32_t& r3, uint32_t addr) {
    asm volatile("ldmatrix.sync.aligned.m8n8.x4.shared.b16 {%0,%1,%2,%3}, [%4];"
                 : "=r"(r0), "=r"(r1), "=r"(r2), "=r"(r3) : "r"(addr));
}

__device__ __forceinline__ void mma_f16(float& c0, float& c1, float& c2, float& c3,
                                        uint32_t a0, uint32_t a1, uint32_t a2, uint32_t a3,
                                        uint32_t b0, uint32_t b1) {
    asm volatile(
        "mma.sync.aligned.m16n8k16.row.col.f32.f16.f16.f32 "
        "{%0,%1,%2,%3}, {%4,%5,%6,%7}, {%8,%9}, {%0,%1,%2,%3};"
        : "+f"(c0), "+f"(c1), "+f"(c2), "+f"(c3)
        : "r"(a0), "r"(a1), "r"(a2), "r"(a3), "r"(b0), "r"(b1));
}

// relaxed L2 data ops + acquire/release flag ops (per-lane SPSC protocol)
__device__ __forceinline__ void  stcg_f(float* p, float v) {
    asm volatile("st.global.cg.f32 [%0], %1;" :: "l"(p), "f"(v) : "memory");
}
__device__ __forceinline__ float ldcg_f(const float* p) {
    float v; asm volatile("ld.global.cg.f32 %0, [%1];" : "=f"(v) : "l"(p)); return v;
}
__device__ __forceinline__ void  st_rel(int* p, int v) {
    asm volatile("st.release.gpu.global.s32 [%0], %1;" :: "l"(p), "r"(v) : "memory");
}
__device__ __forceinline__ int   ld_acq(const int* p) {
    int v; asm volatile("ld.acquire.gpu.global.s32 %0, [%1];" : "=r"(v) : "l"(p)); return v;
}

// ===========================================================================
// reset kernel: flags + ticket (runs every launch; graph-replay safe)
// ===========================================================================
__global__ __launch_bounds__(256) void reset_kernel()
{
    int i = blockIdx.x * 256 + threadIdx.x;
    if (i < B_SZ * NC * H_SZ) g_flag[i] = 0;
    if (i == 0) g_ticket = 0;
}

// ===========================================================================
// fp32 -> fp16 conversion pass (8 elems/thread, vectorized)
// ===========================================================================
__global__ __launch_bounds__(256) void cvt_kernel(const float* __restrict__ src,
                                                  __half* __restrict__ dst)
{
    size_t i = ((size_t)blockIdx.x * 256 + threadIdx.x) * 8;
    float4 v0 = *reinterpret_cast<const float4*>(src + i);
    float4 v1 = *reinterpret_cast<const float4*>(src + i + 4);
    __half2 h[4];
    h[0] = __floats2half2_rn(v0.x, v0.y);
    h[1] = __floats2half2_rn(v0.z, v0.w);
    h[2] = __floats2half2_rn(v1.x, v1.y);
    h[3] = __floats2half2_rn(v1.z, v1.w);
    *reinterpret_cast<uint4*>(dst + i) = *reinterpret_cast<uint4*>(h);
}

// ===========================================================================
// Fused GEMM + gates + per-lane decoupled-lookback scan -> final h directly.
// 256 threads = 8 warps: 2 warp-rows (64 M) x 4 warp-cols (32 N).
// CTA tile M=128 x N=128 (64 h) == exactly one scan chunk.
// Ticket remap guarantees chunk CTAs start in schedule order (lookback-safe).
// Per-lane flags: each h lane's (A,Bc,Hinc) is released by the thread that
// wrote it and acquired by the thread that reads it — no cross-thread fences.
// ===========================================================================
#define BM 128
#define BN 128
#define BK 64
#define STAGES 3
#define PITCHW 36
#define PITCHB (PITCHW * 4)             // 144 bytes
#define A_WORDS (BM * PITCHW)           // 4608
#define B_WORDS (BN * PITCHW)           // 4608
#define STAGE_WORDS (A_WORDS + B_WORDS) // 9216
#define SMEM_DYN (STAGES * STAGE_WORDS * 4)   // 110592 bytes
#define NCHUNK (D_SZ / BK)              // 16
#define EPI_PITCH 65

__global__ void __launch_bounds__(256, 2)
gemm_kernel(const float* __restrict__ bz,
            const float* __restrict__ bh,
            float* __restrict__ out)
{
    extern __shared__ uint32_t smem[];
    __shared__ int s_ticket;
    __shared__ float s_carry[64];
    const uint32_t smem_b = smem_u32(smem);

    const int tid = threadIdx.x;
    const int wid = tid >> 5;
    const int lid = tid & 31;
    const int gr  = lid >> 2;
    const int gc  = lid & 3;
    const int wm  = wid & 1;
    const int wn  = wid >> 1;

    if (tid == 0) s_ticket = atomicAdd(&g_ticket, 1);
    __syncthreads();
    const int tk   = s_ticket;
    const int hx   = tk & (NHX - 1);      // h-block (fast-varying)
    const int mblk = tk >> 4;             // global m-block = batch*NC + chunk
    const int m0   = mblk * BM;
    const int h0   = hx * 64;
    const int bidx = mblk >> 5;           // batch
    const int cidx = mblk & (NC - 1);     // chunk within batch

    // ---- per-lane ldmatrix byte offsets (within a stage)
    const uint32_t aLane = (uint32_t)(wm * 64 + (lid & 15)) * PITCHB + (uint32_t)(lid >> 4) * 16;
    const uint32_t bLane = A_WORDS * 4
        + (uint32_t)(wn * 32 + ((lid >> 4) & 1) * 8 + (lid & 7)) * PITCHB
        + (uint32_t)((lid >> 3) & 1) * 16;

    auto load_chunk = [&](int c, int s) {
        const int k0 = c * BK;
        const uint32_t abase = smem_b + (uint32_t)s * STAGE_WORDS * 4;
        const uint32_t bbase = abase + A_WORDS * 4;
        #pragma unroll
        for (int j = 0; j < 4; j++) {
            int idx = tid + j * 256;
            int r = idx >> 3, q = idx & 7;
            cp_async16(abase + r * PITCHB + q * 16,
                       &g_xh[(size_t)(m0 + r) * D_SZ + k0 + q * 8]);
        }
        #pragma unroll
        for (int j = 0; j < 4; j++) {
            int idx = tid + j * 256;
            int n = idx >> 3, q = idx & 7;
            const __half* W = (n & 1) ? g_whh : g_wzh;
            cp_async16(bbase + n * PITCHB + q * 16,
                       &W[(size_t)(h0 + (n >> 1)) * D_SZ + k0 + q * 8]);
        }
    };

    float acc[4][4][4];
    #pragma unroll
    for (int i = 0; i < 4; i++)
        #pragma unroll
        for (int j = 0; j < 4; j++)
            #pragma unroll
            for (int t = 0; t < 4; t++)
                acc[i][j][t] = 0.0f;

    load_chunk(0, 0); CP_COMMIT();
    load_chunk(1, 1); CP_COMMIT();

    for (int i = 0; i < NCHUNK; i++) {
        if (i == NCHUNK - 1) { CP_WAIT(0); } else { CP_WAIT(1); }
        __syncthreads();
        if (i + 2 < NCHUNK) { load_chunk(i + 2, (i + 2) % STAGES); CP_COMMIT(); }

        const uint32_t sbase = smem_b + (uint32_t)(i % STAGES) * STAGE_WORDS * 4;

        #pragma unroll
        for (int ks = 0; ks < 4; ks++) {
            const uint32_t koff = (uint32_t)ks * 32;
            uint32_t af[4][4], bf[2][4];
            #pragma unroll
            for (int mi = 0; mi < 4; mi++)
                ldsm_x4(af[mi][0], af[mi][1], af[mi][2], af[mi][3],
                        sbase + aLane + (uint32_t)mi * 16 * PITCHB + koff);
            #pragma unroll
            for (int p = 0; p < 2; p++)
                ldsm_x4(bf[p][0], bf[p][1], bf[p][2], bf[p][3],
                        sbase + bLane + (uint32_t)p * 16 * PITCHB + koff);
            #pragma unroll
            for (int mi = 0; mi < 4; mi++) {
                #pragma unroll
                for (int p = 0; p < 2; p++) {
                    mma_f16(acc[mi][2*p  ][0], acc[mi][2*p  ][1],
                            acc[mi][2*p  ][2], acc[mi][2*p  ][3],
                            af[mi][0], af[mi][1], af[mi][2], af[mi][3],
                            bf[p][0], bf[p][1]);
                    mma_f16(acc[mi][2*p+1][0], acc[mi][2*p+1][1],
                            acc[mi][2*p+1][2], acc[mi][2*p+1][3],
                            af[mi][0], af[mi][1], af[mi][2], af[mi][3],
                            bf[p][2], bf[p][3]);
                }
            }
        }
    }

    // ================= epilogue =================
    __syncthreads();
    float* sa = (float*)smem;                    // [128][EPI_PITCH]
    float* sb = sa + BM * EPI_PITCH;

    // 1) gate math -> smem (fp32)
    #pragma unroll
    for (int mi = 0; mi < 4; mi++) {
        #pragma unroll
        for (int nj = 0; nj < 4; nj++) {
            const int hl = wn * 16 + nj * 4 + gc;
            const float bzv = __ldg(&bz[h0 + hl]);
            const float bhv = __ldg(&bh[h0 + hl]);
            #pragma unroll
            for (int half = 0; half < 2; half++) {
                const int r = wm * 64 + mi * 16 + gr + half * 8;
                float k  = acc[mi][nj][half * 2 + 0] + bzv;
                float th = acc[mi][nj][half * 2 + 1] + bhv;
                float em  = __expf(-fabsf(k));
                float inv = 1.0f / (1.0f + em);
                float z, a;
                if (k >= 0.0f) { z = inv;      a = em * inv; }
                else           { z = em * inv; a = inv;      }
                float g;
                if (th >= 0.0f) g = th + 0.5f;
                else            g = 1.0f / (1.0f + __expf(-th));
                sa[r * EPI_PITCH + hl] = a;
                sb[r * EPI_PITCH + hl] = z * g;
            }
        }
    }
    __syncthreads();

    // 2+3) per-lane summary, publish, lookback, publish inclusive
    if (tid < 64) {
        const int hl = tid;
        const int j0 = (bidx * NC + cidx) * H_SZ + h0 + hl;

        float A_self = 1.0f, B_self = 0.0f;
        #pragma unroll 8
        for (int t = 0; t < CL; t++) {
            float a  = sa[t * EPI_PITCH + hl];
            float bb = sb[t * EPI_PITCH + hl];
            A_self *= a;
            B_self = fmaf(a, B_self, bb);
        }
        stcg_f(&g_A [j0], A_self);
        stcg_f(&g_Bc[j0], B_self);
        st_rel(&g_flag[j0], 1);          // release: orders the two data stores

        float carry = 0.0f;
        if (cidx > 0) {
            float Aacc = 1.0f, Bacc = 0.0f;
            int cc = cidx - 1;
            while (true) {
                const int j2 = (bidx * NC + cc) * H_SZ + h0 + hl;
                int f;
                do { f = ld_acq(&g_flag[j2]); } while (f == 0);   // acquire
                if (f >= 2) {
                    carry = fmaf(Aacc, ldcg_f(&g_Hinc[j2]), Bacc);
                    break;
                }
                float Ap = ldcg_f(&g_A [j2]);
                float Bp = ldcg_f(&g_Bc[j2]);
                Bacc = fmaf(Aacc, Bp, Bacc);
                Aacc *= Ap;
                if (--cc < 0) { carry = Bacc; break; }
            }
        }
        stcg_f(&g_Hinc[j0], fmaf(A_self, carry, B_self));
        st_rel(&g_flag[j0], 2);          // release: orders the Hinc store
        s_carry[hl] = carry;
    }
    __syncthreads();

    // 4) rescan chunk with carry (in smem), then coalesced out stores
    if (tid < 64) {
        const int hl = tid;
        float hacc = s_carry[hl];
        #pragma unroll 8
        for (int t = 0; t < CL; t++) {
            hacc = fmaf(sa[t * EPI_PITCH + hl], hacc, sb[t * EPI_PITCH + hl]);
            sa[t * EPI_PITCH + hl] = hacc;
        }
    }
    __syncthreads();
    #pragma unroll 4
    for (int e = tid; e < BM * 64; e += 256) {
        const int m = e >> 6, h = e & 63;
        out[(size_t)(m0 + m) * H_SZ + h0 + h] = sa[m * EPI_PITCH + h];
    }
}

// ===========================================================================
extern "C" void kernel_launch(void* const* d_in, const int* in_sizes, int n_in,
                              void* d_out, int out_size)
{
    const float* x  = (const float*)d_in[0];
    const float* Wz = (const float*)d_in[1];
    const float* bz = (const float*)d_in[2];
    const float* Wh = (const float*)d_in[3];
    const float* bh = (const float*)d_in[4];
    float* out = (float*)d_out;

    cudaFuncSetAttribute(gemm_kernel,
                         cudaFuncAttributeMaxDynamicSharedMemorySize, SMEM_DYN);

    reset_kernel<<<(B_SZ * NC * H_SZ + 255) / 256, 256>>>();

    // fp32 -> fp16 conversion
    __half* xh;  cudaGetSymbolAddress((void**)&xh,  g_xh);
    __half* wzh; cudaGetSymbolAddress((void**)&wzh, g_wzh);
    __half* whh; cudaGetSymbolAddress((void**)&whh, g_whh);
    cvt_kernel<<<(M_TOT * D_SZ) / (256 * 8), 256>>>(x,  xh);
    cvt_kernel<<<(H_SZ * D_SZ) / (256 * 8), 256>>>(Wz, wzh);
    cvt_kernel<<<(H_SZ * D_SZ) / (256 * 8), 256>>>(Wh, whh);

    dim3 ggrid(NHX, M_TOT / BM);   // (16, 256); actual tile via ticket remap
    gemm_kernel<<<ggrid, 256, SMEM_DYN>>>(bz, bh, out);
}